// round 13
// baseline (speedup 1.0000x reference)
#include <cuda_runtime.h>
#include <cuda_fp16.h>
#include <cstdint>
#include <math.h>

#define BB 8
#define NN 2048
#define FIN 256
#define FOUT 128
#define BN (BB*NN)   // 16384 rows total

#define JT 64                     // j-tile (K of the attn mma loop)
#define NTILES (NN/JT)            // 32
#define STRIDE 72                 // b16 elems per smem row (144 B) - conflict-free ldmatrix
#define TILE_BYTES (128*STRIDE*2)          // 18432 (128-row tile)

#define ATT_A_BYTES (64*STRIDE*2)          // 9216  (64-row A tile)
#define ATT_B_BYTES (128*STRIDE*2)         // 18432 (128-row B tile)
#define ATT_STAGE (ATT_A_BYTES + ATT_B_BYTES)   // 27648
#define ATT_DSMEM (2*ATT_STAGE)            // 55296

#define WT_STRIDE 264                      // halfs per s_W row (528 B), LDSM conflict-free
#define WT_BYTES (FOUT*WT_STRIDE*2)        // 67584
#define WH_DSMEM (2*TILE_BYTES + WT_BYTES) // A0, A1, s_W = 104448

// Named barrier ids (0 reserved for __syncthreads)
#define BAR_FULL0  1
#define BAR_FULL1  2
#define BAR_EMPTY0 3
#define BAR_EMPTY1 4
#define BAR_CONS   5

// Scratch (static device arrays; allocation is forbidden)
__device__ __half g_WhT[(size_t)BB * FOUT * NN];       // [b][f][n] Wh fp16 (single)
__device__ float  g_s1[BN], g_s2[BN];

// ---------------------------------------------------------------------------
__device__ __forceinline__ uint32_t smem_u32(const void* p) {
    uint32_t a;
    asm("{ .reg .u64 t; cvta.to.shared.u64 t, %1; cvt.u32.u64 %0, t; }"
        : "=r"(a) : "l"(p));
    return a;
}

#define LDSM_X4(r, addr) \
    asm volatile("ldmatrix.sync.aligned.m8n8.x4.shared.b16 {%0,%1,%2,%3}, [%4];" \
        : "=r"((r)[0]), "=r"((r)[1]), "=r"((r)[2]), "=r"((r)[3]) : "r"(addr))

#define CP_ASYNC16(dst, src) \
    asm volatile("cp.async.cg.shared.global [%0], [%1], 16;" :: "r"(dst), "l"(src) : "memory")
#define CP_COMMIT() asm volatile("cp.async.commit_group;" ::: "memory")
#define CP_WAIT0()  asm volatile("cp.async.wait_group 0;" ::: "memory")

#define BAR_ARRIVE(id, cnt) \
    asm volatile("bar.arrive %0, %1;" :: "r"(id), "r"(cnt) : "memory")
#define BAR_SYNC(id, cnt) \
    asm volatile("bar.sync %0, %1;" :: "r"(id), "r"(cnt) : "memory")

__device__ __forceinline__ void mma16816(float* c, const uint32_t* a, const uint32_t* b) {
    asm volatile(
        "mma.sync.aligned.m16n8k16.row.col.f32.f16.f16.f32 "
        "{%0,%1,%2,%3}, {%4,%5,%6,%7}, {%8,%9}, {%0,%1,%2,%3};"
        : "+f"(c[0]), "+f"(c[1]), "+f"(c[2]), "+f"(c[3])
        : "r"(a[0]), "r"(a[1]), "r"(a[2]), "r"(a[3]), "r"(b[0]), "r"(b[1]));
}

__device__ __forceinline__ uint4 pack8h(__half2 a, __half2 b, __half2 c, __half2 d) {
    uint4 v;
    v.x = *(unsigned*)&a; v.y = *(unsigned*)&b;
    v.z = *(unsigned*)&c; v.w = *(unsigned*)&d;
    return v;
}

// ---------------------------------------------------------------------------
// Kernel 1: Wh = h @ W via HMMA, single fp16 product (unchanged).
// ---------------------------------------------------------------------------
__global__ __launch_bounds__(256) void k_wh(const float* __restrict__ h,
                                            const float* __restrict__ W,
                                            const float* __restrict__ a) {
    extern __shared__ char wsm[];
    __shared__ float s_u1[FIN], s_u2[FIN];
    __shared__ float s_a[2 * FOUT];

    const int t = threadIdx.x, w = t >> 5, lane = t & 31;
    const int bx = blockIdx.x;
    const size_t row0 = (size_t)bx * 128;
    const int b  = bx >> 4;
    const int n0 = (bx & 15) * 128;

    char* A0   = wsm;                      // A double buffer
    char* s_Wc = wsm + 2 * TILE_BYTES;     // persistent W^T fp16
    __half* sW = (__half*)s_Wc;
    const uint32_t sWu = smem_u32(s_Wc);

    // ---- prologue: load a; transpose W -> fp16 smem; u1/u2 fp32 ----
    s_a[t] = a[t];
    __syncthreads();
    {
        const int kk = w * 32;     // warp's 32 k-rows
#pragma unroll 4
        for (int i = 0; i < 32; i++) {
            const int k = kk + i;
            float wv[4];
#pragma unroll
            for (int p = 0; p < 4; p++) wv[p] = W[k * FOUT + lane + p * 32];
            float u1p = 0.f, u2p = 0.f;
#pragma unroll
            for (int p = 0; p < 4; p++) {
                u1p += wv[p] * s_a[lane + p * 32];
                u2p += wv[p] * s_a[FOUT + lane + p * 32];
            }
#pragma unroll
            for (int p = 0; p < 4; p++)
                sW[(lane + p * 32) * WT_STRIDE + k] = __float2half_rn(wv[p]);
#pragma unroll
            for (int o = 16; o; o >>= 1) {
                u1p += __shfl_xor_sync(0xFFFFFFFFu, u1p, o);
                u2p += __shfl_xor_sync(0xFFFFFFFFu, u2p, o);
            }
            if (lane == 0) { s_u1[k] = u1p; s_u2[k] = u2p; }
        }
    }

    const int row = t >> 1, fq = t & 1;   // staging role: row 0..127, k half
    const float* __restrict__ hrow = h + (row0 + row) * (size_t)FIN + fq * 32;

    const int wm = w & 1, wn = w >> 1;
    const uint32_t aRow = (uint32_t)((wm * 64 + (lane & 15)) * (STRIDE * 2) + (lane >> 4) * 16);
    const uint32_t bRowW = (uint32_t)((wn * 32 + (lane & 15)) * (WT_STRIDE * 2) + (lane >> 4) * 16);

    float c[4][4][4];
#pragma unroll
    for (int mt = 0; mt < 4; mt++)
#pragma unroll
        for (int nt = 0; nt < 4; nt++)
#pragma unroll
            for (int r = 0; r < 4; r++) c[mt][nt][r] = 0.f;

    float s1p = 0.f, s2p = 0.f;

    // prefetch h chunk 0
    float4 hv[8];
    {
        const float4* hp = (const float4*)(hrow);
#pragma unroll
        for (int g = 0; g < 8; g++) hv[g] = hp[g];
    }
    __syncthreads();   // s_W, s_u ready

    for (int kc = 0; kc < 4; kc++) {
        const int k0 = kc * 64;
        const int s = kc & 1;
        char* A_t = A0 + s * TILE_BYTES;

        // ---- score partials + convert/store A (fp16) from prefetched h ----
        {
            const float4* u1v = (const float4*)&s_u1[k0 + fq * 32];
            const float4* u2v = (const float4*)&s_u2[k0 + fq * 32];
#pragma unroll
            for (int g = 0; g < 8; g++) {
                const float4 u1 = u1v[g], u2 = u2v[g];
                s1p += hv[g].x * u1.x + hv[g].y * u1.y + hv[g].z * u1.z + hv[g].w * u1.w;
                s2p += hv[g].x * u2.x + hv[g].y * u2.y + hv[g].z * u2.z + hv[g].w * u2.w;
            }
            char* ap = A_t + row * (STRIDE * 2) + fq * 64;
#pragma unroll
            for (int g = 0; g < 4; g++) {
                const float4 v0 = hv[2 * g], v1 = hv[2 * g + 1];
                *(uint4*)(ap + g * 16) = pack8h(__floats2half2_rn(v0.x, v0.y),
                                                __floats2half2_rn(v0.z, v0.w),
                                                __floats2half2_rn(v1.x, v1.y),
                                                __floats2half2_rn(v1.z, v1.w));
            }
        }
        __syncthreads();

        // ---- prefetch next h chunk under the mma ----
        if (kc < 3) {
            const float4* hp = (const float4*)(hrow + (kc + 1) * 64);
#pragma unroll
            for (int g = 0; g < 8; g++) hv[g] = hp[g];
        }

        // ---- mma: 4 k-steps of 16, 1 product; B from persistent s_W ----
        const uint32_t sA = smem_u32(A_t);
#pragma unroll
        for (int ks = 0; ks < 4; ks++) {
            const uint32_t kOffA = ks * 32;
            const uint32_t kOffB = (uint32_t)(k0 * 2 + ks * 32);
            uint32_t a4[4][4], b4[4][2];
#pragma unroll
            for (int mt = 0; mt < 4; mt++) {
                const uint32_t mOff = aRow + mt * 16 * (STRIDE * 2) + kOffA;
                LDSM_X4(a4[mt], sA + mOff);
            }
#pragma unroll
            for (int np = 0; np < 2; np++) {
                const uint32_t nOff = bRowW + np * 16 * (WT_STRIDE * 2) + kOffB;
                uint32_t q[4];
                LDSM_X4(q, sWu + nOff);
                b4[2*np][0] = q[0]; b4[2*np][1] = q[2];
                b4[2*np+1][0] = q[1]; b4[2*np+1][1] = q[3];
            }
#pragma unroll
            for (int mt = 0; mt < 4; mt++)
#pragma unroll
                for (int nt = 0; nt < 4; nt++)
                    mma16816(c[mt][nt], a4[mt], b4[nt]);
        }
    }

    // ---- scores: pair-reduce and write ----
    s1p += __shfl_xor_sync(0xFFFFFFFFu, s1p, 1);
    s2p += __shfl_xor_sync(0xFFFFFFFFu, s2p, 1);
    if (fq == 0) {
        const size_t r = row0 + row;
        g_s1[r] = s1p;
        g_s2[r] = s2p;
    }

    // ---- WhT fp16 transposed store via smem (reuses A buffers) ----
    __syncthreads();
    __half* s_T = (__half*)wsm;   // [128 f][136]
    const int qrow = lane >> 2, qcol = 2 * (lane & 3);
#pragma unroll
    for (int mt = 0; mt < 4; mt++) {
        const int r0 = wm * 64 + mt * 16 + qrow;
        const int r1 = r0 + 8;
#pragma unroll
        for (int nt = 0; nt < 4; nt++) {
            const int c0 = wn * 32 + nt * 8 + qcol;
            s_T[c0 * 136 + r0]       = __float2half_rn(c[mt][nt][0]);
            s_T[(c0 + 1) * 136 + r0] = __float2half_rn(c[mt][nt][1]);
            s_T[c0 * 136 + r1]       = __float2half_rn(c[mt][nt][2]);
            s_T[(c0 + 1) * 136 + r1] = __float2half_rn(c[mt][nt][3]);
        }
    }
    __syncthreads();
    {
        const int f = t >> 1, part = t & 1;
        const uint4* src = (const uint4*)&s_T[f * 136 + part * 64];
        uint4* dst = (uint4*)&g_WhT[((size_t)(b * FOUT + f)) * NN + n0 + part * 64];
#pragma unroll
        for (int i = 0; i < 8; i++) dst[i] = src[i];
    }
}

// ---------------------------------------------------------------------------
// Kernel 2: fused attention, warp-specialized. 256 threads, CTA = 64i x 128f,
// 2 CTAs/SM. Warps 0-3 producers (weights + B cp.async), warps 4-7 consumers
// (HMMA 32x64 warp tile + ones-column Z). 2-stage ring via named barriers.
//
// Barrier-reuse safety: FULL_s arrivals for tile jt+2 can only happen after
// the producer passed EMPTY_s (jt+2), which requires consumer EMPTY_s arrivals
// issued after the consumer passed FULL_s release for tile jt. So all 256
// participants of a barrier phase complete it before any arrival of the next
// phase on the same id.
// ---------------------------------------------------------------------------
__global__ __launch_bounds__(256, 2) void k_attn(const int* __restrict__ adj,
                                                 float* __restrict__ out) {
    extern __shared__ char dsm[];
    __shared__ float s_Zc[64];
    __shared__ __half s_E2h[NN];          // 4 KB
    __shared__ __half s_F2h[NN];          // 4 KB
    __shared__ float s_red[8];

    const int t = threadIdx.x, lane = t & 31;
    const int b = blockIdx.y, i0 = blockIdx.x * 64;
    const size_t bn = (size_t)b * NN;
    const uint32_t dsm_u = smem_u32(dsm);

    // ---- prologue (all 256): read s2, reduce M2, build s_E2h/s_F2h ----
    const float4 v2a = ((const float4*)(g_s2 + bn))[2 * t];
    const float4 v2b = ((const float4*)(g_s2 + bn))[2 * t + 1];
    float mloc = fmaxf(fmaxf(fmaxf(v2a.x, v2a.y), fmaxf(v2a.z, v2a.w)),
                       fmaxf(fmaxf(v2b.x, v2b.y), fmaxf(v2b.z, v2b.w)));
#pragma unroll
    for (int o = 16; o; o >>= 1) mloc = fmaxf(mloc, __shfl_xor_sync(0xFFFFFFFFu, mloc, o));
    if (lane == 0) s_red[t >> 5] = mloc;
    __syncthreads();
    float M2 = s_red[0];
#pragma unroll
    for (int i = 1; i < 8; i++) M2 = fmaxf(M2, s_red[i]);

    {
        const float sv[8] = { v2a.x, v2a.y, v2a.z, v2a.w, v2b.x, v2b.y, v2b.z, v2b.w };
        uint4 ev, fv;
#pragma unroll
        for (int k = 0; k < 4; k++) {
            const float d0 = sv[2*k] - M2, d1 = sv[2*k+1] - M2;
            ((__half2*)&ev)[k] = __floats2half2_rn(expf(d0), expf(d1));
            ((__half2*)&fv)[k] = __floats2half2_rn(expf(0.2f * d0), expf(0.2f * d1));
        }
        *(uint4*)&s_E2h[8 * t] = ev;
        *(uint4*)&s_F2h[8 * t] = fv;
    }
    __syncthreads();   // s_E2h/s_F2h ready for producers

    if (t < 128) {
        // =================== PRODUCER (warps 0-3) ===================
        const int prow = t >> 1;          // 0..63
        const int pjh  = (t & 1) * 32;    // j half within tile

        const float s1r = g_s1[bn + i0 + prow];
        const float xm  = s1r + M2;
        const float m   = xm > 0.f ? xm : 0.2f * xm;
        const __half2 E1E1 = __half2half2(__float2half_rn(expf(xm - m)));
        const __half2 F1F1 = __half2half2(__float2half_rn(expf(0.2f * xm - m)));
        const int* __restrict__ adjrow = adj + (bn + i0 + prow) * (size_t)NN;

        // B copy: thread t copies Wh row f = t (0..127), full 64 halfs
        const __half* __restrict__ whpB = g_WhT + ((size_t)b * FOUT + t) * NN;
        const uint32_t bDst = (uint32_t)(ATT_A_BYTES + t * (STRIDE * 2));

        // adj prefetch for tile 0
        int4 radj[8];
        {
            const int4* am = (const int4*)(adjrow + pjh);
#pragma unroll
            for (int q = 0; q < 8; q++) radj[q] = am[q];
        }

        for (int jt = 0; jt < NTILES; jt++) {
            const int s = jt & 1;
            if (jt >= 2) BAR_SYNC(BAR_EMPTY0 + s, 256);

            // issue B cp.async for this tile into stage s
            {
                const uint32_t bd = dsm_u + s * ATT_STAGE + bDst;
                const __half* src = whpB + jt * JT;
#pragma unroll
                for (int g = 0; g < 8; g++)
                    CP_ASYNC16(bd + g * 16, src + g * 8);
                CP_COMMIT();
            }

            // build A tile: 32 weights = 16 half2
            {
                const int jg0 = jt * JT + pjh;
                unsigned ea[16], fa[16];
                {
                    const uint4* ep = (const uint4*)&s_E2h[jg0];
                    const uint4* fp = (const uint4*)&s_F2h[jg0];
#pragma unroll
                    for (int g = 0; g < 4; g++) {
                        const uint4 e = ep[g], f = fp[g];
                        ea[4*g] = e.x; ea[4*g+1] = e.y; ea[4*g+2] = e.z; ea[4*g+3] = e.w;
                        fa[4*g] = f.x; fa[4*g+1] = f.y; fa[4*g+2] = f.z; fa[4*g+3] = f.w;
                    }
                }
                unsigned cw[16];
#pragma unroll
                for (int q = 0; q < 8; q++) {
                    const int4 mv = radj[q];
                    {
                        __half2 pe = __hmul2(E1E1, *(const __half2*)&ea[2*q]);
                        __half2 pf = __hmul2(F1F1, *(const __half2*)&fa[2*q]);
                        __half2 cm = __hmax2(pe, pf);
                        unsigned msk = (mv.x > 0 ? 0x0000FFFFu : 0u)
                                     | (mv.y > 0 ? 0xFFFF0000u : 0u);
                        cw[2*q] = (*(unsigned*)&cm) & msk;
                    }
                    {
                        __half2 pe = __hmul2(E1E1, *(const __half2*)&ea[2*q+1]);
                        __half2 pf = __hmul2(F1F1, *(const __half2*)&fa[2*q+1]);
                        __half2 cm = __hmax2(pe, pf);
                        unsigned msk = (mv.z > 0 ? 0x0000FFFFu : 0u)
                                     | (mv.w > 0 ? 0xFFFF0000u : 0u);
                        cw[2*q+1] = (*(unsigned*)&cm) & msk;
                    }
                }
                char* ap = dsm + s * ATT_STAGE + prow * (STRIDE * 2) + pjh * 2;
#pragma unroll
                for (int g = 0; g < 4; g++) {
                    uint4 v;
                    v.x = cw[4*g]; v.y = cw[4*g+1]; v.z = cw[4*g+2]; v.w = cw[4*g+3];
                    *(uint4*)(ap + g * 16) = v;
                }
            }

            // prefetch adj for next tile (latency hidden under next phases)
            if (jt + 1 < NTILES) {
                const int4* am = (const int4*)(adjrow + (jt + 1) * JT + pjh);
#pragma unroll
                for (int q = 0; q < 8; q++) radj[q] = am[q];
            }

            CP_WAIT0();                       // this thread's B copies done
            BAR_ARRIVE(BAR_FULL0 + s, 256);   // stage s ready
        }
        // producers done; all arrivals issued, safe to exit
    } else {
        // =================== CONSUMER (warps 4-7) ===================
        const int cw_id = (t - 128) >> 5;    // 0..3
        const int wm = cw_id & 1, wn = cw_id >> 1;
        const uint32_t aRow = (uint32_t)((wm * 32 + (lane & 15)) * (STRIDE * 2) + (lane >> 4) * 16);
        const uint32_t bRow = (uint32_t)(ATT_A_BYTES
                             + (wn * 64 + (lane & 15)) * (STRIDE * 2) + (lane >> 4) * 16);

        float c[2][8][4];
#pragma unroll
        for (int mt = 0; mt < 2; mt++)
#pragma unroll
            for (int nt = 0; nt < 8; nt++)
#pragma unroll
                for (int r = 0; r < 4; r++) c[mt][nt][r] = 0.f;

        float cz[2][4];
#pragma unroll
        for (int mt = 0; mt < 2; mt++)
#pragma unroll
            for (int r = 0; r < 4; r++) cz[mt][r] = 0.f;
        const uint32_t ones_b[2] = { 0x3C003C00u, 0x3C003C00u };

        for (int jt = 0; jt < NTILES; jt++) {
            const int s = jt & 1;
            BAR_SYNC(BAR_FULL0 + s, 256);     // wait stage s ready

            const uint32_t sA = dsm_u + s * ATT_STAGE;
#pragma unroll
            for (int ks = 0; ks < 4; ks++) {
                const uint32_t kOff = ks * 32;
                uint32_t a4[2][4], b4[8][2];
#pragma unroll
                for (int mt = 0; mt < 2; mt++) {
                    const uint32_t mOff = aRow + mt * 16 * (STRIDE * 2) + kOff;
                    LDSM_X4(a4[mt], sA + mOff);
                }
#pragma unroll
                for (int np = 0; np < 4; np++) {
                    const uint32_t nOff = bRow + np * 16 * (STRIDE * 2) + kOff;
                    uint32_t q[4];
                    LDSM_X4(q, sA + nOff);
                    b4[2*np][0] = q[0]; b4[2*np][1] = q[2];
                    b4[2*np+1][0] = q[1]; b4[2*np+1][1] = q[3];
                }
#pragma unroll
                for (int mt = 0; mt < 2; mt++)
#pragma unroll
                    for (int nt = 0; nt < 8; nt++)
                        mma16816(c[mt][nt], a4[mt], b4[nt]);
                if (wn == 0) {
#pragma unroll
                    for (int mt = 0; mt < 2; mt++)
                        mma16816(cz[mt], a4[mt], ones_b);
                }
            }

            BAR_ARRIVE(BAR_EMPTY0 + s, 256);  // stage s free
        }

        // ---- Z from ones-column accumulators (consumer-only barrier) ----
        const int qrow = lane >> 2, qcol = 2 * (lane & 3);
        if (wn == 0 && (lane & 3) == 0) {
#pragma unroll
            for (int mt = 0; mt < 2; mt++) {
                s_Zc[wm * 32 + mt * 16 + qrow]     = cz[mt][0];
                s_Zc[wm * 32 + mt * 16 + qrow + 8] = cz[mt][2];
            }
        }
        BAR_SYNC(BAR_CONS, 128);

        // ---- normalize + ELU + store ----
#pragma unroll
        for (int mt = 0; mt < 2; mt++) {
            const int r0 = wm * 32 + mt * 16 + qrow;
            const int r1 = r0 + 8;
            const float zi0 = 1.0f / s_Zc[r0];
            const float zi1 = 1.0f / s_Zc[r1];
            float* op0 = out + (bn + i0 + r0) * (size_t)FOUT;
            float* op1 = out + (bn + i0 + r1) * (size_t)FOUT;
#pragma unroll
            for (int nt = 0; nt < 8; nt++) {
                const int col = wn * 64 + nt * 8 + qcol;
                float x0 = c[mt][nt][0] * zi0;
                float x1 = c[mt][nt][1] * zi0;
                float x2 = c[mt][nt][2] * zi1;
                float x3 = c[mt][nt][3] * zi1;
                float2 v0, v1;
                v0.x = x0 > 0.f ? x0 : expm1f(x0);
                v0.y = x1 > 0.f ? x1 : expm1f(x1);
                v1.x = x2 > 0.f ? x2 : expm1f(x2);
                v1.y = x3 > 0.f ? x3 : expm1f(x3);
                *(float2*)(op0 + col) = v0;
                *(float2*)(op1 + col) = v1;
            }
        }
    }
}

// ---------------------------------------------------------------------------
extern "C" void kernel_launch(void* const* d_in, const int* in_sizes, int n_in,
                              void* d_out, int out_size) {
    const float* h = nullptr; const int* adj = nullptr;
    const float* W = nullptr; const float* a = nullptr;
    for (int i = 0; i < n_in; i++) {
        switch (in_sizes[i]) {
            case 4194304:  h   = (const float*)d_in[i]; break;
            case 33554432: adj = (const int*)d_in[i];   break;
            case 32768:    W   = (const float*)d_in[i]; break;
            case 256:      a   = (const float*)d_in[i]; break;
        }
    }
    float* out = (float*)d_out;

    static bool attr_set = false;
    if (!attr_set) {
        cudaFuncSetAttribute(k_wh, cudaFuncAttributeMaxDynamicSharedMemorySize,
                             WH_DSMEM);
        cudaFuncSetAttribute(k_attn, cudaFuncAttributeMaxDynamicSharedMemorySize,
                             ATT_DSMEM);
        attr_set = true;
    }

    k_wh<<<BN / 128, 256, WH_DSMEM>>>(h, W, a);
    k_attn<<<dim3(NN / 64, BB), 256, ATT_DSMEM>>>(adj, out);
}

// round 14
// speedup vs baseline: 1.0345x; 1.0345x over previous
#include <cuda_runtime.h>
#include <cuda_fp16.h>
#include <cstdint>
#include <math.h>

#define BB 8
#define NN 2048
#define FIN 256
#define FOUT 128
#define BN (BB*NN)   // 16384 rows total

#define JT 64                     // j-tile (K of the attn mma loop)
#define NTILES (NN/JT)            // 32
#define STRIDE 72                 // b16 elems per smem row (144 B) - conflict-free ldmatrix
#define TILE_BYTES (128*STRIDE*2)          // 18432 (128-row tile)

#define ATT_A_BYTES (64*STRIDE*2)          // 9216  (64-row A tile)
#define ATT_B_BYTES (128*STRIDE*2)         // 18432 (128-row B tile)
#define ATT_STAGE (ATT_A_BYTES + ATT_B_BYTES)   // 27648
#define ATT_DSMEM (2*ATT_STAGE)            // 55296

#define WT_STRIDE 264                      // halfs per s_W row (528 B), LDSM conflict-free
#define WT_BYTES (FOUT*WT_STRIDE*2)        // 67584
#define WH_DSMEM (2*TILE_BYTES + WT_BYTES) // A0, A1, s_W = 104448

// Scratch (static device arrays; allocation is forbidden)
__device__ __half g_WhT[(size_t)BB * FOUT * NN];       // [b][f][n] Wh fp16 (single)
__device__ float  g_s1[BN], g_s2[BN];

// ---------------------------------------------------------------------------
__device__ __forceinline__ uint32_t smem_u32(const void* p) {
    uint32_t a;
    asm("{ .reg .u64 t; cvta.to.shared.u64 t, %1; cvt.u32.u64 %0, t; }"
        : "=r"(a) : "l"(p));
    return a;
}

#define LDSM_X4(r, addr) \
    asm volatile("ldmatrix.sync.aligned.m8n8.x4.shared.b16 {%0,%1,%2,%3}, [%4];" \
        : "=r"((r)[0]), "=r"((r)[1]), "=r"((r)[2]), "=r"((r)[3]) : "r"(addr))

#define CP_ASYNC16(dst, src) \
    asm volatile("cp.async.cg.shared.global [%0], [%1], 16;" :: "r"(dst), "l"(src) : "memory")
#define CP_COMMIT() asm volatile("cp.async.commit_group;" ::: "memory")
#define CP_WAIT0()  asm volatile("cp.async.wait_group 0;" ::: "memory")

__device__ __forceinline__ void mma16816(float* c, const uint32_t* a, const uint32_t* b) {
    asm volatile(
        "mma.sync.aligned.m16n8k16.row.col.f32.f16.f16.f32 "
        "{%0,%1,%2,%3}, {%4,%5,%6,%7}, {%8,%9}, {%0,%1,%2,%3};"
        : "+f"(c[0]), "+f"(c[1]), "+f"(c[2]), "+f"(c[3])
        : "r"(a[0]), "r"(a[1]), "r"(a[2]), "r"(a[3]), "r"(b[0]), "r"(b[1]));
}

__device__ __forceinline__ uint4 pack8h(__half2 a, __half2 b, __half2 c, __half2 d) {
    uint4 v;
    v.x = *(unsigned*)&a; v.y = *(unsigned*)&b;
    v.z = *(unsigned*)&c; v.w = *(unsigned*)&d;
    return v;
}

// ---------------------------------------------------------------------------
// Kernel 1: Wh = h @ W via HMMA, single fp16 product. Self-contained:
// prologue transposes W to fp16 smem + computes u1/u2 (fp32 exact).
// Fused exact scores (s1 = h.u1, s2 = h.u2) + writes; WhT fp16 out.
// ---------------------------------------------------------------------------
__global__ __launch_bounds__(256) void k_wh(const float* __restrict__ h,
                                            const float* __restrict__ W,
                                            const float* __restrict__ a) {
    extern __shared__ char wsm[];
    __shared__ float s_u1[FIN], s_u2[FIN];
    __shared__ float s_a[2 * FOUT];

    const int t = threadIdx.x, w = t >> 5, lane = t & 31;
    const int bx = blockIdx.x;
    const size_t row0 = (size_t)bx * 128;
    const int b  = bx >> 4;
    const int n0 = (bx & 15) * 128;

    char* A0   = wsm;                      // A double buffer
    char* s_Wc = wsm + 2 * TILE_BYTES;     // persistent W^T fp16
    __half* sW = (__half*)s_Wc;
    const uint32_t sWu = smem_u32(s_Wc);

    // ---- prologue: load a; transpose W -> fp16 smem; u1/u2 fp32 ----
    s_a[t] = a[t];
    __syncthreads();
    {
        const int kk = w * 32;     // warp's 32 k-rows
#pragma unroll 4
        for (int i = 0; i < 32; i++) {
            const int k = kk + i;
            float wv[4];
#pragma unroll
            for (int p = 0; p < 4; p++) wv[p] = W[k * FOUT + lane + p * 32];
            float u1p = 0.f, u2p = 0.f;
#pragma unroll
            for (int p = 0; p < 4; p++) {
                u1p += wv[p] * s_a[lane + p * 32];
                u2p += wv[p] * s_a[FOUT + lane + p * 32];
            }
#pragma unroll
            for (int p = 0; p < 4; p++)
                sW[(lane + p * 32) * WT_STRIDE + k] = __float2half_rn(wv[p]);
#pragma unroll
            for (int o = 16; o; o >>= 1) {
                u1p += __shfl_xor_sync(0xFFFFFFFFu, u1p, o);
                u2p += __shfl_xor_sync(0xFFFFFFFFu, u2p, o);
            }
            if (lane == 0) { s_u1[k] = u1p; s_u2[k] = u2p; }
        }
    }

    const int row = t >> 1, fq = t & 1;   // staging role: row 0..127, k half
    const float* __restrict__ hrow = h + (row0 + row) * (size_t)FIN + fq * 32;

    const int wm = w & 1, wn = w >> 1;
    const uint32_t aRow = (uint32_t)((wm * 64 + (lane & 15)) * (STRIDE * 2) + (lane >> 4) * 16);
    const uint32_t bRowW = (uint32_t)((wn * 32 + (lane & 15)) * (WT_STRIDE * 2) + (lane >> 4) * 16);

    float c[4][4][4];
#pragma unroll
    for (int mt = 0; mt < 4; mt++)
#pragma unroll
        for (int nt = 0; nt < 4; nt++)
#pragma unroll
            for (int r = 0; r < 4; r++) c[mt][nt][r] = 0.f;

    float s1p = 0.f, s2p = 0.f;

    // prefetch h chunk 0
    float4 hv[8];
    {
        const float4* hp = (const float4*)(hrow);
#pragma unroll
        for (int g = 0; g < 8; g++) hv[g] = hp[g];
    }
    __syncthreads();   // s_W, s_u ready

    for (int kc = 0; kc < 4; kc++) {
        const int k0 = kc * 64;
        const int s = kc & 1;
        char* A_t = A0 + s * TILE_BYTES;

        // ---- score partials + convert/store A (fp16) from prefetched h ----
        {
            const float4* u1v = (const float4*)&s_u1[k0 + fq * 32];
            const float4* u2v = (const float4*)&s_u2[k0 + fq * 32];
#pragma unroll
            for (int g = 0; g < 8; g++) {
                const float4 u1 = u1v[g], u2 = u2v[g];
                s1p += hv[g].x * u1.x + hv[g].y * u1.y + hv[g].z * u1.z + hv[g].w * u1.w;
                s2p += hv[g].x * u2.x + hv[g].y * u2.y + hv[g].z * u2.z + hv[g].w * u2.w;
            }
            char* ap = A_t + row * (STRIDE * 2) + fq * 64;
#pragma unroll
            for (int g = 0; g < 4; g++) {
                const float4 v0 = hv[2 * g], v1 = hv[2 * g + 1];
                *(uint4*)(ap + g * 16) = pack8h(__floats2half2_rn(v0.x, v0.y),
                                                __floats2half2_rn(v0.z, v0.w),
                                                __floats2half2_rn(v1.x, v1.y),
                                                __floats2half2_rn(v1.z, v1.w));
            }
        }
        __syncthreads();

        // ---- prefetch next h chunk under the mma ----
        if (kc < 3) {
            const float4* hp = (const float4*)(hrow + (kc + 1) * 64);
#pragma unroll
            for (int g = 0; g < 8; g++) hv[g] = hp[g];
        }

        // ---- mma: 4 k-steps of 16, 1 product; B from persistent s_W ----
        const uint32_t sA = smem_u32(A_t);
#pragma unroll
        for (int ks = 0; ks < 4; ks++) {
            const uint32_t kOffA = ks * 32;
            const uint32_t kOffB = (uint32_t)(k0 * 2 + ks * 32);
            uint32_t a4[4][4], b4[4][2];
#pragma unroll
            for (int mt = 0; mt < 4; mt++) {
                const uint32_t mOff = aRow + mt * 16 * (STRIDE * 2) + kOffA;
                LDSM_X4(a4[mt], sA + mOff);
            }
#pragma unroll
            for (int np = 0; np < 2; np++) {
                const uint32_t nOff = bRowW + np * 16 * (WT_STRIDE * 2) + kOffB;
                uint32_t q[4];
                LDSM_X4(q, sWu + nOff);
                b4[2*np][0] = q[0]; b4[2*np][1] = q[2];
                b4[2*np+1][0] = q[1]; b4[2*np+1][1] = q[3];
            }
#pragma unroll
            for (int mt = 0; mt < 4; mt++)
#pragma unroll
                for (int nt = 0; nt < 4; nt++)
                    mma16816(c[mt][nt], a4[mt], b4[nt]);
        }
    }

    // ---- scores: pair-reduce and write ----
    s1p += __shfl_xor_sync(0xFFFFFFFFu, s1p, 1);
    s2p += __shfl_xor_sync(0xFFFFFFFFu, s2p, 1);
    if (fq == 0) {
        const size_t r = row0 + row;
        g_s1[r] = s1p;
        g_s2[r] = s2p;
    }

    // ---- WhT fp16 transposed store via smem (reuses A buffers) ----
    __syncthreads();
    __half* s_T = (__half*)wsm;   // [128 f][136]
    const int qrow = lane >> 2, qcol = 2 * (lane & 3);
#pragma unroll
    for (int mt = 0; mt < 4; mt++) {
        const int r0 = wm * 64 + mt * 16 + qrow;
        const int r1 = r0 + 8;
#pragma unroll
        for (int nt = 0; nt < 4; nt++) {
            const int c0 = wn * 32 + nt * 8 + qcol;
            s_T[c0 * 136 + r0]       = __float2half_rn(c[mt][nt][0]);
            s_T[(c0 + 1) * 136 + r0] = __float2half_rn(c[mt][nt][1]);
            s_T[c0 * 136 + r1]       = __float2half_rn(c[mt][nt][2]);
            s_T[(c0 + 1) * 136 + r1] = __float2half_rn(c[mt][nt][3]);
        }
    }
    __syncthreads();
    {
        const int f = t >> 1, part = t & 1;
        const uint4* src = (const uint4*)&s_T[f * 136 + part * 64];
        uint4* dst = (uint4*)&g_WhT[((size_t)(b * FOUT + f)) * NN + n0 + part * 64];
#pragma unroll
        for (int i = 0; i < 8; i++) dst[i] = src[i];
    }
}

// ---------------------------------------------------------------------------
// Kernel 2: fused attention (round-12 structure), 256 threads, 64i x 128f,
// 2 CTAs/SM. SIMD max-identity weights with byte_perm masks (adj in {0,1});
// adj prefetched 2 tiles deep; B via cp.async; Z via ones-column HMMA.
// ---------------------------------------------------------------------------
__global__ __launch_bounds__(256, 2) void k_attn(const int* __restrict__ adj,
                                                 float* __restrict__ out) {
    extern __shared__ char dsm[];
    __shared__ float s_Zc[64];
    __shared__ __half s_E2h[NN];          // 4 KB
    __shared__ __half s_F2h[NN];          // 4 KB
    __shared__ float s_red[8];

    const int t = threadIdx.x, w = t >> 5, lane = t & 31;
    const int b = blockIdx.y, i0 = blockIdx.x * 64;
    const size_t bn = (size_t)b * NN;
    const uint32_t dsm_u = smem_u32(dsm);

    // ---- prologue: read s2 (8/thread), reduce M2, build s_E2h/s_F2h ----
    const float4 v2a = ((const float4*)(g_s2 + bn))[2 * t];
    const float4 v2b = ((const float4*)(g_s2 + bn))[2 * t + 1];
    float mloc = fmaxf(fmaxf(fmaxf(v2a.x, v2a.y), fmaxf(v2a.z, v2a.w)),
                       fmaxf(fmaxf(v2b.x, v2b.y), fmaxf(v2b.z, v2b.w)));
#pragma unroll
    for (int o = 16; o; o >>= 1) mloc = fmaxf(mloc, __shfl_xor_sync(0xFFFFFFFFu, mloc, o));
    if (lane == 0) s_red[w] = mloc;
    __syncthreads();
    float M2 = s_red[0];
#pragma unroll
    for (int i = 1; i < 8; i++) M2 = fmaxf(M2, s_red[i]);

    {
        const float sv[8] = { v2a.x, v2a.y, v2a.z, v2a.w, v2b.x, v2b.y, v2b.z, v2b.w };
        uint4 ev, fv;
#pragma unroll
        for (int k = 0; k < 4; k++) {
            const float d0 = sv[2*k] - M2, d1 = sv[2*k+1] - M2;
            ((__half2*)&ev)[k] = __floats2half2_rn(expf(d0), expf(d1));
            ((__half2*)&fv)[k] = __floats2half2_rn(expf(0.2f * d0), expf(0.2f * d1));
        }
        *(uint4*)&s_E2h[8 * t] = ev;
        *(uint4*)&s_F2h[8 * t] = fv;
    }

    // ---- c-phase mapping ----
    const int row = t >> 2;           // 0..63
    const int jq  = (t & 3) * 16;

    const float s1r = g_s1[bn + i0 + row];
    const float xm  = s1r + M2;
    const float m   = xm > 0.f ? xm : 0.2f * xm;
    const __half2 E1E1 = __half2half2(__float2half_rn(expf(xm - m)));
    const __half2 F1F1 = __half2half2(__float2half_rn(expf(0.2f * xm - m)));
    const int* __restrict__ adjrow = adj + (bn + i0 + row) * (size_t)NN;

    // ---- B-copy mapping ----
    const int fB = t >> 1, partB = t & 1;
    const __half* __restrict__ whpB = g_WhT + ((size_t)b * FOUT + fB) * NN + partB * 32;
    const uint32_t bDst = (uint32_t)(ATT_A_BYTES + fB * (STRIDE * 2) + partB * 64);

    // ---- mma-phase addressing: warp tile 32(m) x 32(n) ----
    const int wm = w & 1, wn = w >> 1;
    const uint32_t aRow = (uint32_t)((wm * 32 + (lane & 15)) * (STRIDE * 2) + (lane >> 4) * 16);
    const uint32_t bRow = (uint32_t)(ATT_A_BYTES
                         + (wn * 32 + (lane & 15)) * (STRIDE * 2) + (lane >> 4) * 16);

    float c[2][4][4];
#pragma unroll
    for (int mt = 0; mt < 2; mt++)
#pragma unroll
        for (int nt = 0; nt < 4; nt++)
#pragma unroll
            for (int r = 0; r < 4; r++) c[mt][nt][r] = 0.f;

    // Z accumulators (ones-column mma; only wn==0 warps use them)
    float cz[2][4];
#pragma unroll
    for (int mt = 0; mt < 2; mt++)
#pragma unroll
        for (int r = 0; r < 4; r++) cz[mt][r] = 0.f;
    const uint32_t ones_b[2] = { 0x3C003C00u, 0x3C003C00u };

    // B tile 0 via cp.async; adj tiles 0 and 1 into a 2-deep register ring
    {
        const uint32_t bd = dsm_u + bDst;
        CP_ASYNC16(bd,      whpB);
        CP_ASYNC16(bd + 16, whpB + 8);
        CP_ASYNC16(bd + 32, whpB + 16);
        CP_ASYNC16(bd + 48, whpB + 24);
        CP_COMMIT();
    }
    int4 radj[2][4];
    {
        const int4* am0 = (const int4*)(adjrow + jq);
        const int4* am1 = (const int4*)(adjrow + JT + jq);
#pragma unroll
        for (int q = 0; q < 4; q++) { radj[0][q] = am0[q]; radj[1][q] = am1[q]; }
    }
    __syncthreads();   // s_E2h/s_F2h ready

    for (int jt = 0; jt < NTILES; jt++) {
        const int s = jt & 1;
        char* A_t = dsm + s * ATT_STAGE;
        const int jg0 = jt * JT + jq;

        // ---- build c tile (16 weights = 8 half2), byte_perm masks ----
        {
            const uint4 e0 = *(const uint4*)&s_E2h[jg0];
            const uint4 e1 = *(const uint4*)&s_E2h[jg0 + 8];
            const uint4 f0 = *(const uint4*)&s_F2h[jg0];
            const uint4 f1 = *(const uint4*)&s_F2h[jg0 + 8];
            const unsigned ea[8] = { e0.x, e0.y, e0.z, e0.w, e1.x, e1.y, e1.z, e1.w };
            const unsigned fa[8] = { f0.x, f0.y, f0.z, f0.w, f1.x, f1.y, f1.z, f1.w };
            unsigned cw[8];
#pragma unroll
            for (int q = 0; q < 4; q++) {
                const int4 mv = radj[s][q];
                {
                    __half2 pe = __hmul2(E1E1, *(const __half2*)&ea[2*q]);
                    __half2 pf = __hmul2(F1F1, *(const __half2*)&fa[2*q]);
                    __half2 cm = __hmax2(pe, pf);
                    // adj in {0,1}: -v = 0 or all-ones; PRMT packs the two 16-bit masks
                    unsigned msk = __byte_perm((unsigned)(-mv.x), (unsigned)(-mv.y), 0x5410);
                    cw[2*q] = (*(unsigned*)&cm) & msk;
                }
                {
                    __half2 pe = __hmul2(E1E1, *(const __half2*)&ea[2*q+1]);
                    __half2 pf = __hmul2(F1F1, *(const __half2*)&fa[2*q+1]);
                    __half2 cm = __hmax2(pe, pf);
                    unsigned msk = __byte_perm((unsigned)(-mv.z), (unsigned)(-mv.w), 0x5410);
                    cw[2*q+1] = (*(unsigned*)&cm) & msk;
                }
            }
            char* ap = A_t + row * (STRIDE * 2) + jq * 2;
            uint4 v0, v1;
            v0.x = cw[0]; v0.y = cw[1]; v0.z = cw[2]; v0.w = cw[3];
            v1.x = cw[4]; v1.y = cw[5]; v1.z = cw[6]; v1.w = cw[7];
            *(uint4*)(ap)      = v0;
            *(uint4*)(ap + 16) = v1;
        }

        CP_WAIT0();        // this tile's B arrived (this thread's copies)
        __syncthreads();   // everyone's B + A visible; prev mma done

        // ---- issue next B (cp.async into other stage); adj jt+2 into ring ----
        if (jt + 1 < NTILES) {
            const uint32_t bd = dsm_u + (s ^ 1) * ATT_STAGE + bDst;
            const __half* src = whpB + (jt + 1) * JT;
            CP_ASYNC16(bd,      src);
            CP_ASYNC16(bd + 16, src + 8);
            CP_ASYNC16(bd + 32, src + 16);
            CP_ASYNC16(bd + 48, src + 24);
        }
        CP_COMMIT();
        if (jt + 2 < NTILES) {
            const int4* am = (const int4*)(adjrow + (jt + 2) * JT + jq);
#pragma unroll
            for (int q = 0; q < 4; q++) radj[s][q] = am[q];
        }

        // ---- mma: 4 k-steps, warp tile 32x32 (+ ones column on wn==0) ----
        const uint32_t sA = dsm_u + s * ATT_STAGE;
#pragma unroll
        for (int ks = 0; ks < 4; ks++) {
            const uint32_t kOff = ks * 32;
            uint32_t a4[2][4], b4[4][2];
#pragma unroll
            for (int mt = 0; mt < 2; mt++) {
                const uint32_t mOff = aRow + mt * 16 * (STRIDE * 2) + kOff;
                LDSM_X4(a4[mt], sA + mOff);
            }
#pragma unroll
            for (int np = 0; np < 2; np++) {
                const uint32_t nOff = bRow + np * 16 * (STRIDE * 2) + kOff;
                uint32_t q[4];
                LDSM_X4(q, sA + nOff);
                b4[2*np][0] = q[0]; b4[2*np][1] = q[2];
                b4[2*np+1][0] = q[1]; b4[2*np+1][1] = q[3];
            }
#pragma unroll
            for (int mt = 0; mt < 2; mt++)
#pragma unroll
                for (int nt = 0; nt < 4; nt++)
                    mma16816(c[mt][nt], a4[mt], b4[nt]);
            if (wn == 0) {
#pragma unroll
                for (int mt = 0; mt < 2; mt++)
                    mma16816(cz[mt], a4[mt], ones_b);
            }
        }
    }

    // ---- Z from ones-column accumulators ----
    const int qrow = lane >> 2, qcol = 2 * (lane & 3);
    if (wn == 0 && (lane & 3) == 0) {
#pragma unroll
        for (int mt = 0; mt < 2; mt++) {
            s_Zc[wm * 32 + mt * 16 + qrow]     = cz[mt][0];
            s_Zc[wm * 32 + mt * 16 + qrow + 8] = cz[mt][2];
        }
    }
    __syncthreads();

    // ---- normalize + ELU + store ----
#pragma unroll
    for (int mt = 0; mt < 2; mt++) {
        const int r0 = wm * 32 + mt * 16 + qrow;
        const int r1 = r0 + 8;
        const float zi0 = 1.0f / s_Zc[r0];
        const float zi1 = 1.0f / s_Zc[r1];
        float* op0 = out + (bn + i0 + r0) * (size_t)FOUT;
        float* op1 = out + (bn + i0 + r1) * (size_t)FOUT;
#pragma unroll
        for (int nt = 0; nt < 4; nt++) {
            const int col = wn * 32 + nt * 8 + qcol;
            float x0 = c[mt][nt][0] * zi0;
            float x1 = c[mt][nt][1] * zi0;
            float x2 = c[mt][nt][2] * zi1;
            float x3 = c[mt][nt][3] * zi1;
            float2 v0, v1;
            v0.x = x0 > 0.f ? x0 : expm1f(x0);
            v0.y = x1 > 0.f ? x1 : expm1f(x1);
            v1.x = x2 > 0.f ? x2 : expm1f(x2);
            v1.y = x3 > 0.f ? x3 : expm1f(x3);
            *(float2*)(op0 + col) = v0;
            *(float2*)(op1 + col) = v1;
        }
    }
}

// ---------------------------------------------------------------------------
extern "C" void kernel_launch(void* const* d_in, const int* in_sizes, int n_in,
                              void* d_out, int out_size) {
    const float* h = nullptr; const int* adj = nullptr;
    const float* W = nullptr; const float* a = nullptr;
    for (int i = 0; i < n_in; i++) {
        switch (in_sizes[i]) {
            case 4194304:  h   = (const float*)d_in[i]; break;
            case 33554432: adj = (const int*)d_in[i];   break;
            case 32768:    W   = (const float*)d_in[i]; break;
            case 256:      a   = (const float*)d_in[i]; break;
        }
    }
    float* out = (float*)d_out;

    static bool attr_set = false;
    if (!attr_set) {
        cudaFuncSetAttribute(k_wh, cudaFuncAttributeMaxDynamicSharedMemorySize,
                             WH_DSMEM);
        cudaFuncSetAttribute(k_attn, cudaFuncAttributeMaxDynamicSharedMemorySize,
                             ATT_DSMEM);
        attr_set = true;
    }

    k_wh<<<BN / 128, 256, WH_DSMEM>>>(h, W, a);
    k_attn<<<dim3(NN / 64, BB), 256, ATT_DSMEM>>>(adj, out);
}

// round 15
// speedup vs baseline: 1.2879x; 1.2449x over previous
#include <cuda_runtime.h>
#include <cuda_fp16.h>
#include <cstdint>
#include <math.h>

#define BB 8
#define NN 2048
#define FIN 256
#define FOUT 128
#define BN (BB*NN)   // 16384 rows total

#define JT 64                     // j-tile (K of the attn mma loop)
#define NTILES (NN/JT)            // 32
#define STRIDE 72                 // b16 elems per smem row (144 B) - conflict-free ldmatrix
#define TILE_BYTES (128*STRIDE*2)          // 18432 (128-row tile)

#define ATT_A_BYTES (64*STRIDE*2)          // 9216  (64-row A tile)
#define ATT_B_BYTES (128*STRIDE*2)         // 18432 (128-row B tile)
#define ATT_STAGE (ATT_A_BYTES + ATT_B_BYTES)   // 27648
#define ATT_DSMEM (2*ATT_STAGE)            // 55296

#define WT_STRIDE 264                      // halfs per s_W row (528 B), LDSM conflict-free
#define WT_BYTES (FOUT*WT_STRIDE*2)        // 67584
#define WH_DSMEM (2*TILE_BYTES + WT_BYTES) // A0, A1, s_W = 104448

// Scratch (static device arrays; allocation is forbidden)
__device__ __half g_WhT[(size_t)BB * FOUT * NN];       // [b][f][n] Wh fp16 (single)
__device__ float  g_s1[BN], g_s2[BN];

// ---------------------------------------------------------------------------
__device__ __forceinline__ uint32_t smem_u32(const void* p) {
    uint32_t a;
    asm("{ .reg .u64 t; cvta.to.shared.u64 t, %1; cvt.u32.u64 %0, t; }"
        : "=r"(a) : "l"(p));
    return a;
}

#define LDSM_X4(r, addr) \
    asm volatile("ldmatrix.sync.aligned.m8n8.x4.shared.b16 {%0,%1,%2,%3}, [%4];" \
        : "=r"((r)[0]), "=r"((r)[1]), "=r"((r)[2]), "=r"((r)[3]) : "r"(addr))

#define CP_ASYNC16(dst, src) \
    asm volatile("cp.async.cg.shared.global [%0], [%1], 16;" :: "r"(dst), "l"(src) : "memory")
#define CP_COMMIT() asm volatile("cp.async.commit_group;" ::: "memory")
#define CP_WAIT0()  asm volatile("cp.async.wait_group 0;" ::: "memory")

__device__ __forceinline__ void mma16816(float* c, const uint32_t* a, const uint32_t* b) {
    asm volatile(
        "mma.sync.aligned.m16n8k16.row.col.f32.f16.f16.f32 "
        "{%0,%1,%2,%3}, {%4,%5,%6,%7}, {%8,%9}, {%0,%1,%2,%3};"
        : "+f"(c[0]), "+f"(c[1]), "+f"(c[2]), "+f"(c[3])
        : "r"(a[0]), "r"(a[1]), "r"(a[2]), "r"(a[3]), "r"(b[0]), "r"(b[1]));
}

__device__ __forceinline__ uint4 pack8h(__half2 a, __half2 b, __half2 c, __half2 d) {
    uint4 v;
    v.x = *(unsigned*)&a; v.y = *(unsigned*)&b;
    v.z = *(unsigned*)&c; v.w = *(unsigned*)&d;
    return v;
}

// ---------------------------------------------------------------------------
// Kernel 1: Wh = h @ W via HMMA, single fp16 product. Self-contained:
// prologue transposes W to fp16 smem + computes u1/u2 (fp32 exact).
// Fused exact scores (s1 = h.u1, s2 = h.u2) + writes; WhT fp16 out.
// ---------------------------------------------------------------------------
__global__ __launch_bounds__(256) void k_wh(const float* __restrict__ h,
                                            const float* __restrict__ W,
                                            const float* __restrict__ a) {
    extern __shared__ char wsm[];
    __shared__ float s_u1[FIN], s_u2[FIN];
    __shared__ float s_a[2 * FOUT];

    const int t = threadIdx.x, w = t >> 5, lane = t & 31;
    const int bx = blockIdx.x;
    const size_t row0 = (size_t)bx * 128;
    const int b  = bx >> 4;
    const int n0 = (bx & 15) * 128;

    char* A0   = wsm;                      // A double buffer
    char* s_Wc = wsm + 2 * TILE_BYTES;     // persistent W^T fp16
    __half* sW = (__half*)s_Wc;
    const uint32_t sWu = smem_u32(s_Wc);

    // ---- prologue: load a; transpose W -> fp16 smem; u1/u2 fp32 ----
    s_a[t] = a[t];
    __syncthreads();
    {
        const int kk = w * 32;     // warp's 32 k-rows
#pragma unroll 4
        for (int i = 0; i < 32; i++) {
            const int k = kk + i;
            float wv[4];
#pragma unroll
            for (int p = 0; p < 4; p++) wv[p] = W[k * FOUT + lane + p * 32];
            float u1p = 0.f, u2p = 0.f;
#pragma unroll
            for (int p = 0; p < 4; p++) {
                u1p += wv[p] * s_a[lane + p * 32];
                u2p += wv[p] * s_a[FOUT + lane + p * 32];
            }
#pragma unroll
            for (int p = 0; p < 4; p++)
                sW[(lane + p * 32) * WT_STRIDE + k] = __float2half_rn(wv[p]);
#pragma unroll
            for (int o = 16; o; o >>= 1) {
                u1p += __shfl_xor_sync(0xFFFFFFFFu, u1p, o);
                u2p += __shfl_xor_sync(0xFFFFFFFFu, u2p, o);
            }
            if (lane == 0) { s_u1[k] = u1p; s_u2[k] = u2p; }
        }
    }

    const int row = t >> 1, fq = t & 1;   // staging role: row 0..127, k half
    const float* __restrict__ hrow = h + (row0 + row) * (size_t)FIN + fq * 32;

    const int wm = w & 1, wn = w >> 1;
    const uint32_t aRow = (uint32_t)((wm * 64 + (lane & 15)) * (STRIDE * 2) + (lane >> 4) * 16);
    const uint32_t bRowW = (uint32_t)((wn * 32 + (lane & 15)) * (WT_STRIDE * 2) + (lane >> 4) * 16);

    float c[4][4][4];
#pragma unroll
    for (int mt = 0; mt < 4; mt++)
#pragma unroll
        for (int nt = 0; nt < 4; nt++)
#pragma unroll
            for (int r = 0; r < 4; r++) c[mt][nt][r] = 0.f;

    float s1p = 0.f, s2p = 0.f;

    // prefetch h chunk 0
    float4 hv[8];
    {
        const float4* hp = (const float4*)(hrow);
#pragma unroll
        for (int g = 0; g < 8; g++) hv[g] = hp[g];
    }
    __syncthreads();   // s_W, s_u ready

    for (int kc = 0; kc < 4; kc++) {
        const int k0 = kc * 64;
        const int s = kc & 1;
        char* A_t = A0 + s * TILE_BYTES;

        // ---- score partials + convert/store A (fp16) from prefetched h ----
        {
            const float4* u1v = (const float4*)&s_u1[k0 + fq * 32];
            const float4* u2v = (const float4*)&s_u2[k0 + fq * 32];
#pragma unroll
            for (int g = 0; g < 8; g++) {
                const float4 u1 = u1v[g], u2 = u2v[g];
                s1p += hv[g].x * u1.x + hv[g].y * u1.y + hv[g].z * u1.z + hv[g].w * u1.w;
                s2p += hv[g].x * u2.x + hv[g].y * u2.y + hv[g].z * u2.z + hv[g].w * u2.w;
            }
            char* ap = A_t + row * (STRIDE * 2) + fq * 64;
#pragma unroll
            for (int g = 0; g < 4; g++) {
                const float4 v0 = hv[2 * g], v1 = hv[2 * g + 1];
                *(uint4*)(ap + g * 16) = pack8h(__floats2half2_rn(v0.x, v0.y),
                                                __floats2half2_rn(v0.z, v0.w),
                                                __floats2half2_rn(v1.x, v1.y),
                                                __floats2half2_rn(v1.z, v1.w));
            }
        }
        __syncthreads();

        // ---- prefetch next h chunk under the mma ----
        if (kc < 3) {
            const float4* hp = (const float4*)(hrow + (kc + 1) * 64);
#pragma unroll
            for (int g = 0; g < 8; g++) hv[g] = hp[g];
        }

        // ---- mma: 4 k-steps of 16, 1 product; B from persistent s_W ----
        const uint32_t sA = smem_u32(A_t);
#pragma unroll
        for (int ks = 0; ks < 4; ks++) {
            const uint32_t kOffA = ks * 32;
            const uint32_t kOffB = (uint32_t)(k0 * 2 + ks * 32);
            uint32_t a4[4][4], b4[4][2];
#pragma unroll
            for (int mt = 0; mt < 4; mt++) {
                const uint32_t mOff = aRow + mt * 16 * (STRIDE * 2) + kOffA;
                LDSM_X4(a4[mt], sA + mOff);
            }
#pragma unroll
            for (int np = 0; np < 2; np++) {
                const uint32_t nOff = bRowW + np * 16 * (WT_STRIDE * 2) + kOffB;
                uint32_t q[4];
                LDSM_X4(q, sWu + nOff);
                b4[2*np][0] = q[0]; b4[2*np][1] = q[2];
                b4[2*np+1][0] = q[1]; b4[2*np+1][1] = q[3];
            }
#pragma unroll
            for (int mt = 0; mt < 4; mt++)
#pragma unroll
                for (int nt = 0; nt < 4; nt++)
                    mma16816(c[mt][nt], a4[mt], b4[nt]);
        }
    }

    // ---- scores: pair-reduce and write ----
    s1p += __shfl_xor_sync(0xFFFFFFFFu, s1p, 1);
    s2p += __shfl_xor_sync(0xFFFFFFFFu, s2p, 1);
    if (fq == 0) {
        const size_t r = row0 + row;
        g_s1[r] = s1p;
        g_s2[r] = s2p;
    }

    // ---- WhT fp16 transposed store via smem (reuses A buffers) ----
    __syncthreads();
    __half* s_T = (__half*)wsm;   // [128 f][136]
    const int qrow = lane >> 2, qcol = 2 * (lane & 3);
#pragma unroll
    for (int mt = 0; mt < 4; mt++) {
        const int r0 = wm * 64 + mt * 16 + qrow;
        const int r1 = r0 + 8;
#pragma unroll
        for (int nt = 0; nt < 4; nt++) {
            const int c0 = wn * 32 + nt * 8 + qcol;
            s_T[c0 * 136 + r0]       = __float2half_rn(c[mt][nt][0]);
            s_T[(c0 + 1) * 136 + r0] = __float2half_rn(c[mt][nt][1]);
            s_T[c0 * 136 + r1]       = __float2half_rn(c[mt][nt][2]);
            s_T[(c0 + 1) * 136 + r1] = __float2half_rn(c[mt][nt][3]);
        }
    }
    __syncthreads();
    {
        const int f = t >> 1, part = t & 1;
        const uint4* src = (const uint4*)&s_T[f * 136 + part * 64];
        uint4* dst = (uint4*)&g_WhT[((size_t)(b * FOUT + f)) * NN + n0 + part * 64];
#pragma unroll
        for (int i = 0; i < 8; i++) dst[i] = src[i];
    }
}

// ---------------------------------------------------------------------------
// Kernel 2: fused attention (round-12 structure restored), 256 threads,
// CTA = 64i x 128f, 2 CTAs/SM. SIMD max-identity weights with byte_perm
// masks (adj in {0,1}); single-tile adj prefetch (statically indexed regs);
// B via cp.async; Z via ones-column HMMA.
// ---------------------------------------------------------------------------
__global__ __launch_bounds__(256, 2) void k_attn(const int* __restrict__ adj,
                                                 float* __restrict__ out) {
    extern __shared__ char dsm[];
    __shared__ float s_Zc[64];
    __shared__ __half s_E2h[NN];          // 4 KB
    __shared__ __half s_F2h[NN];          // 4 KB
    __shared__ float s_red[8];

    const int t = threadIdx.x, w = t >> 5, lane = t & 31;
    const int b = blockIdx.y, i0 = blockIdx.x * 64;
    const size_t bn = (size_t)b * NN;
    const uint32_t dsm_u = smem_u32(dsm);

    // ---- prologue: read s2 (8/thread), reduce M2, build s_E2h/s_F2h ----
    const float4 v2a = ((const float4*)(g_s2 + bn))[2 * t];
    const float4 v2b = ((const float4*)(g_s2 + bn))[2 * t + 1];
    float mloc = fmaxf(fmaxf(fmaxf(v2a.x, v2a.y), fmaxf(v2a.z, v2a.w)),
                       fmaxf(fmaxf(v2b.x, v2b.y), fmaxf(v2b.z, v2b.w)));
#pragma unroll
    for (int o = 16; o; o >>= 1) mloc = fmaxf(mloc, __shfl_xor_sync(0xFFFFFFFFu, mloc, o));
    if (lane == 0) s_red[w] = mloc;
    __syncthreads();
    float M2 = s_red[0];
#pragma unroll
    for (int i = 1; i < 8; i++) M2 = fmaxf(M2, s_red[i]);

    {
        const float sv[8] = { v2a.x, v2a.y, v2a.z, v2a.w, v2b.x, v2b.y, v2b.z, v2b.w };
        uint4 ev, fv;
#pragma unroll
        for (int k = 0; k < 4; k++) {
            const float d0 = sv[2*k] - M2, d1 = sv[2*k+1] - M2;
            ((__half2*)&ev)[k] = __floats2half2_rn(expf(d0), expf(d1));
            ((__half2*)&fv)[k] = __floats2half2_rn(expf(0.2f * d0), expf(0.2f * d1));
        }
        *(uint4*)&s_E2h[8 * t] = ev;
        *(uint4*)&s_F2h[8 * t] = fv;
    }

    // ---- c-phase mapping ----
    const int row = t >> 2;           // 0..63
    const int jq  = (t & 3) * 16;

    const float s1r = g_s1[bn + i0 + row];
    const float xm  = s1r + M2;
    const float m   = xm > 0.f ? xm : 0.2f * xm;
    const __half2 E1E1 = __half2half2(__float2half_rn(expf(xm - m)));
    const __half2 F1F1 = __half2half2(__float2half_rn(expf(0.2f * xm - m)));
    const int* __restrict__ adjrow = adj + (bn + i0 + row) * (size_t)NN;

    // ---- B-copy mapping ----
    const int fB = t >> 1, partB = t & 1;
    const __half* __restrict__ whpB = g_WhT + ((size_t)b * FOUT + fB) * NN + partB * 32;
    const uint32_t bDst = (uint32_t)(ATT_A_BYTES + fB * (STRIDE * 2) + partB * 64);

    // ---- mma-phase addressing: warp tile 32(m) x 32(n) ----
    const int wm = w & 1, wn = w >> 1;
    const uint32_t aRow = (uint32_t)((wm * 32 + (lane & 15)) * (STRIDE * 2) + (lane >> 4) * 16);
    const uint32_t bRow = (uint32_t)(ATT_A_BYTES
                         + (wn * 32 + (lane & 15)) * (STRIDE * 2) + (lane >> 4) * 16);

    float c[2][4][4];
#pragma unroll
    for (int mt = 0; mt < 2; mt++)
#pragma unroll
        for (int nt = 0; nt < 4; nt++)
#pragma unroll
            for (int r = 0; r < 4; r++) c[mt][nt][r] = 0.f;

    // Z accumulators (ones-column mma; only wn==0 warps use them)
    float cz[2][4];
#pragma unroll
    for (int mt = 0; mt < 2; mt++)
#pragma unroll
        for (int r = 0; r < 4; r++) cz[mt][r] = 0.f;
    const uint32_t ones_b[2] = { 0x3C003C00u, 0x3C003C00u };

    // B tile 0 via cp.async; adj tile 0 into regs (statically indexed)
    {
        const uint32_t bd = dsm_u + bDst;
        CP_ASYNC16(bd,      whpB);
        CP_ASYNC16(bd + 16, whpB + 8);
        CP_ASYNC16(bd + 32, whpB + 16);
        CP_ASYNC16(bd + 48, whpB + 24);
        CP_COMMIT();
    }
    int4 radj[4];
    {
        const int4* am = (const int4*)(adjrow + jq);
#pragma unroll
        for (int q = 0; q < 4; q++) radj[q] = am[q];
    }
    __syncthreads();   // s_E2h/s_F2h ready

    for (int jt = 0; jt < NTILES; jt++) {
        const int s = jt & 1;
        char* A_t = dsm + s * ATT_STAGE;
        const int jg0 = jt * JT + jq;

        // ---- build c tile (16 weights = 8 half2), byte_perm masks ----
        {
            const uint4 e0 = *(const uint4*)&s_E2h[jg0];
            const uint4 e1 = *(const uint4*)&s_E2h[jg0 + 8];
            const uint4 f0 = *(const uint4*)&s_F2h[jg0];
            const uint4 f1 = *(const uint4*)&s_F2h[jg0 + 8];
            const unsigned ea[8] = { e0.x, e0.y, e0.z, e0.w, e1.x, e1.y, e1.z, e1.w };
            const unsigned fa[8] = { f0.x, f0.y, f0.z, f0.w, f1.x, f1.y, f1.z, f1.w };
            unsigned cw[8];
#pragma unroll
            for (int q = 0; q < 4; q++) {
                const int4 mv = radj[q];
                {
                    __half2 pe = __hmul2(E1E1, *(const __half2*)&ea[2*q]);
                    __half2 pf = __hmul2(F1F1, *(const __half2*)&fa[2*q]);
                    __half2 cm = __hmax2(pe, pf);
                    // adj in {0,1}: -v = 0 or all-ones; PRMT packs two 16-bit masks
                    unsigned msk = __byte_perm((unsigned)(-mv.x), (unsigned)(-mv.y), 0x5410);
                    cw[2*q] = (*(unsigned*)&cm) & msk;
                }
                {
                    __half2 pe = __hmul2(E1E1, *(const __half2*)&ea[2*q+1]);
                    __half2 pf = __hmul2(F1F1, *(const __half2*)&fa[2*q+1]);
                    __half2 cm = __hmax2(pe, pf);
                    unsigned msk = __byte_perm((unsigned)(-mv.z), (unsigned)(-mv.w), 0x5410);
                    cw[2*q+1] = (*(unsigned*)&cm) & msk;
                }
            }
            char* ap = A_t + row * (STRIDE * 2) + jq * 2;
            uint4 v0, v1;
            v0.x = cw[0]; v0.y = cw[1]; v0.z = cw[2]; v0.w = cw[3];
            v1.x = cw[4]; v1.y = cw[5]; v1.z = cw[6]; v1.w = cw[7];
            *(uint4*)(ap)      = v0;
            *(uint4*)(ap + 16) = v1;
        }

        CP_WAIT0();        // this tile's B arrived (this thread's copies)
        __syncthreads();   // everyone's B + A visible; prev mma done

        // ---- issue next B (cp.async into other stage) + prefetch adj ----
        if (jt + 1 < NTILES) {
            const uint32_t bd = dsm_u + (s ^ 1) * ATT_STAGE + bDst;
            const __half* src = whpB + (jt + 1) * JT;
            CP_ASYNC16(bd,      src);
            CP_ASYNC16(bd + 16, src + 8);
            CP_ASYNC16(bd + 32, src + 16);
            CP_ASYNC16(bd + 48, src + 24);
            const int4* am = (const int4*)(adjrow + (jt + 1) * JT + jq);
#pragma unroll
            for (int q = 0; q < 4; q++) radj[q] = am[q];
        }
        CP_COMMIT();

        // ---- mma: 4 k-steps, warp tile 32x32 (+ ones column on wn==0) ----
        const uint32_t sA = dsm_u + s * ATT_STAGE;
#pragma unroll
        for (int ks = 0; ks < 4; ks++) {
            const uint32_t kOff = ks * 32;
            uint32_t a4[2][4], b4[4][2];
#pragma unroll
            for (int mt = 0; mt < 2; mt++) {
                const uint32_t mOff = aRow + mt * 16 * (STRIDE * 2) + kOff;
                LDSM_X4(a4[mt], sA + mOff);
            }
#pragma unroll
            for (int np = 0; np < 2; np++) {
                const uint32_t nOff = bRow + np * 16 * (STRIDE * 2) + kOff;
                uint32_t q[4];
                LDSM_X4(q, sA + nOff);
                b4[2*np][0] = q[0]; b4[2*np][1] = q[2];
                b4[2*np+1][0] = q[1]; b4[2*np+1][1] = q[3];
            }
#pragma unroll
            for (int mt = 0; mt < 2; mt++)
#pragma unroll
                for (int nt = 0; nt < 4; nt++)
                    mma16816(c[mt][nt], a4[mt], b4[nt]);
            if (wn == 0) {
#pragma unroll
                for (int mt = 0; mt < 2; mt++)
                    mma16816(cz[mt], a4[mt], ones_b);
            }
        }
    }

    // ---- Z from ones-column accumulators ----
    const int qrow = lane >> 2, qcol = 2 * (lane & 3);
    if (wn == 0 && (lane & 3) == 0) {
#pragma unroll
        for (int mt = 0; mt < 2; mt++) {
            s_Zc[wm * 32 + mt * 16 + qrow]     = cz[mt][0];
            s_Zc[wm * 32 + mt * 16 + qrow + 8] = cz[mt][2];
        }
    }
    __syncthreads();

    // ---- normalize + ELU + store ----
#pragma unroll
    for (int mt = 0; mt < 2; mt++) {
        const int r0 = wm * 32 + mt * 16 + qrow;
        const int r1 = r0 + 8;
        const float zi0 = 1.0f / s_Zc[r0];
        const float zi1 = 1.0f / s_Zc[r1];
        float* op0 = out + (bn + i0 + r0) * (size_t)FOUT;
        float* op1 = out + (bn + i0 + r1) * (size_t)FOUT;
#pragma unroll
        for (int nt = 0; nt < 4; nt++) {
            const int col = wn * 32 + nt * 8 + qcol;
            float x0 = c[mt][nt][0] * zi0;
            float x1 = c[mt][nt][1] * zi0;
            float x2 = c[mt][nt][2] * zi1;
            float x3 = c[mt][nt][3] * zi1;
            float2 v0, v1;
            v0.x = x0 > 0.f ? x0 : expm1f(x0);
            v0.y = x1 > 0.f ? x1 : expm1f(x1);
            v1.x = x2 > 0.f ? x2 : expm1f(x2);
            v1.y = x3 > 0.f ? x3 : expm1f(x3);
            *(float2*)(op0 + col) = v0;
            *(float2*)(op1 + col) = v1;
        }
    }
}

// ---------------------------------------------------------------------------
extern "C" void kernel_launch(void* const* d_in, const int* in_sizes, int n_in,
                              void* d_out, int out_size) {
    const float* h = nullptr; const int* adj = nullptr;
    const float* W = nullptr; const float* a = nullptr;
    for (int i = 0; i < n_in; i++) {
        switch (in_sizes[i]) {
            case 4194304:  h   = (const float*)d_in[i]; break;
            case 33554432: adj = (const int*)d_in[i];   break;
            case 32768:    W   = (const float*)d_in[i]; break;
            case 256:      a   = (const float*)d_in[i]; break;
        }
    }
    float* out = (float*)d_out;

    static bool attr_set = false;
    if (!attr_set) {
        cudaFuncSetAttribute(k_wh, cudaFuncAttributeMaxDynamicSharedMemorySize,
                             WH_DSMEM);
        cudaFuncSetAttribute(k_attn, cudaFuncAttributeMaxDynamicSharedMemorySize,
                             ATT_DSMEM);
        attr_set = true;
    }

    k_wh<<<BN / 128, 256, WH_DSMEM>>>(h, W, a);
    k_attn<<<dim3(NN / 64, BB), 256, ATT_DSMEM>>>(adj, out);
}